// round 3
// baseline (speedup 1.0000x reference)
#include <cuda_runtime.h>

typedef unsigned long long ull;

static constexpr int B = 32;
static constexpr int T = 32768;
static constexpr int H = 64;

// packed fp32x2 FMA: acc.lo += a.lo*b.lo ; acc.hi += a.hi*b.hi
__device__ __forceinline__ void fma2(ull& acc, ull a, ull b) {
    asm("fma.rn.f32x2 %0, %1, %2, %0;" : "+l"(acc) : "l"(a), "l"(b));
}
__device__ __forceinline__ void add2(ull& a, ull b) {
    asm("add.rn.f32x2 %0, %1, %2;" : "=l"(a) : "l"(a), "l"(b));
}
__device__ __forceinline__ ull pack2(float lo, float hi) {
    ull v;
    asm("mov.b64 %0, {%1,%2};" : "=l"(v) : "f"(lo), "f"(hi));
    return v;
}
__device__ __forceinline__ float sum2(ull v) {
    float lo, hi;
    asm("mov.b64 {%0,%1}, %2;" : "=f"(lo), "=f"(hi) : "l"(v));
    return lo + hi;
}
__device__ __forceinline__ float rcpf(float x) {
    float r;
    asm("rcp.approx.ftz.f32 %0, %1;" : "=f"(r) : "f"(x));
    return r;
}
__device__ __forceinline__ float ex2f(float x) {
    float r;
    asm("ex2.approx.ftz.f32 %0, %1;" : "=f"(r) : "f"(x));
    return r;
}
// sigma(v) = 1/(1+e^-v); graceful at extremes (e=inf -> rcp=0)
__device__ __forceinline__ float sigf(float v) {
    float e = ex2f(v * -1.4426950408889634f);
    return rcpf(1.f + e);
}
// tanh(v) = 1 - 2e/(1+e), e = e^{-2v}; clamp only negative side (overflow)
__device__ __forceinline__ float tanhf_fast(float v) {
    v = fmaxf(v, -10.f);
    float e = ex2f(v * -2.885390081777927f);
    float r = rcpf(1.f + e);
    return fmaf(-2.f * e, r, 1.f);
}

// One CTA per batch. 128 threads: pair (2i,2i+1) owns hidden element i.
// Even lane: full-K r-dot + half n-dot.  Odd lane: full-K z-dot + half n-dot.
// Identical instruction stream on both lanes (no divergence); z reaches the
// even lane via one late shfl. One __syncthreads per step, double-buffered h.
__global__ __launch_bounds__(128, 1)
void gru_kernel(const float* __restrict__ x,
                const float* __restrict__ w_ih,
                const float* __restrict__ w_hh,
                const float* __restrict__ b_ih,
                const float* __restrict__ b_hh,
                float* __restrict__ states)   // [B, T, H]
{
    __shared__ __align__(16) float h_sh[2][64];

    const int bb  = blockIdx.x;
    const int tid = threadIdx.x;
    const int i   = tid >> 1;      // hidden element 0..63
    const int hk  = tid & 1;       // 0 -> r row, 1 -> z row; also n K-half

    // stationary weights in registers
    ull w0[32], wn[16];
    {
        const int r0 = i + hk * 64;                      // r or z row
        const ull* p0 = (const ull*)(w_hh + (size_t)r0 * H);
        #pragma unroll
        for (int m = 0; m < 32; m++) w0[m] = p0[m];
        const ull* pn = (const ull*)(w_hh + (size_t)(i + 128) * H + 32 * hk);
        #pragma unroll
        for (int m = 0; m < 16; m++) wn[m] = pn[m];
    }
    const int idx0 = i + hk * 64;
    const float wih0 = w_ih[idx0];
    const float b0   = b_ih[idx0] + b_hh[idx0];          // folded bias (r/z)
    const float wihn = w_ih[i + 128];
    const float bihn = b_ih[i + 128];
    const float bhhn_init = hk ? 0.f : b_hh[i + 128];    // counted once per pair

    if (tid < 64) { h_sh[0][tid] = 0.f; h_sh[1][tid] = 0.f; }
    __syncthreads();

    const float* xb = x + (size_t)bb * T;
    float* sb = states + (size_t)bb * T * H + i;

    float h_prev = 0.f;   // meaningful on even lane only

#define GRU_STEP(XT, RB, WB, TT)                                              \
    do {                                                                      \
        float xt0 = fmaf((XT), wih0, b0);                                     \
        float xtn = fmaf((XT), wihn, bihn);                                   \
        const ulonglong2* hv2 = (const ulonglong2*)h_sh[RB];                  \
        ull a0 = pack2(xt0, 0.f), a1 = 0, a2 = 0, a3 = 0;                     \
        _Pragma("unroll")                                                     \
        for (int m = 0; m < 16; m += 2) {   /* 16 ulonglong2 = all 64 h */    \
            ulonglong2 hA = hv2[m], hB = hv2[m + 1];                          \
            fma2(a0, w0[2 * m + 0], hA.x); fma2(a1, w0[2 * m + 1], hA.y);     \
            fma2(a2, w0[2 * m + 2], hB.x); fma2(a3, w0[2 * m + 3], hB.y);     \
        }                                                                     \
        add2(a0, a1); add2(a2, a3); add2(a0, a2);                             \
        float g = sigf(sum2(a0));               /* r (even) / z (odd) */      \
        const ulonglong2* hn2 = (const ulonglong2*)(h_sh[RB] + 32 * hk);      \
        ull n0 = pack2(bhhn_init, 0.f), n1 = 0;                               \
        _Pragma("unroll")                                                     \
        for (int m = 0; m < 8; m++) {       /* 8 ulonglong2 = 32 h (half) */  \
            ulonglong2 hC = hn2[m];                                           \
            fma2(n0, wn[2 * m + 0], hC.x);                                    \
            fma2(n1, wn[2 * m + 1], hC.y);                                    \
        }                                                                     \
        add2(n0, n1);                                                         \
        float cnh = sum2(n0);                                                 \
        float cn  = cnh + __shfl_xor_sync(0xffffffffu, cnh, 1);               \
        float zz  = __shfl_xor_sync(0xffffffffu, g, 1);                       \
        float narg = fmaf(g, cn, xtn);                                        \
        float n = tanhf_fast(narg);                                           \
        float zh  = zz * h_prev;                                              \
        float omz = 1.f - zz;                                                 \
        float hnew = fmaf(n, omz, zh);          /* (1-z)*n + z*h */           \
        h_prev = hnew;                                                        \
        if (!hk) { h_sh[WB][i] = hnew; sb[(size_t)(TT) * H] = hnew; }         \
        __syncthreads();                                                      \
    } while (0)

    float x0 = __ldg(xb);
    for (int t = 0; t < T; t += 2) {
        float x1 = __ldg(xb + t + 1);
        int tn = (t + 2 < T) ? (t + 2) : (T - 1);
        float xn = __ldg(xb + tn);
        GRU_STEP(x0, 0, 1, t);
        GRU_STEP(x1, 1, 0, t + 1);
        x0 = xn;
    }
#undef GRU_STEP
}

// out[b,t] = dot(states[b,t,:], w_lin) + b_lin + x[b,t]  — parallel epilogue
__global__ __launch_bounds__(256)
void head_kernel(const float* __restrict__ x,
                 const float* __restrict__ states,
                 const float* __restrict__ w_lin,
                 const float* __restrict__ b_lin,
                 float* __restrict__ out)
{
    int idx = blockIdx.x * blockDim.x + threadIdx.x;   // 0 .. B*T-1 exactly
    const float4* s4 = (const float4*)(states + (size_t)idx * H);
    const float4* w4 = (const float4*)w_lin;
    float acc = 0.f;
    #pragma unroll
    for (int m = 0; m < 16; m++) {
        float4 s = __ldg(&s4[m]);
        float4 w = __ldg(&w4[m]);
        acc = fmaf(s.x, w.x, acc);
        acc = fmaf(s.y, w.y, acc);
        acc = fmaf(s.z, w.z, acc);
        acc = fmaf(s.w, w.w, acc);
    }
    out[idx] = acc + __ldg(b_lin) + __ldg(&x[idx]);
}

extern "C" void kernel_launch(void* const* d_in, const int* in_sizes, int n_in,
                              void* d_out, int out_size)
{
    const float* x     = (const float*)d_in[0];
    const float* w_ih  = (const float*)d_in[1];
    const float* w_hh  = (const float*)d_in[2];
    const float* b_ih  = (const float*)d_in[3];
    const float* b_hh  = (const float*)d_in[4];
    const float* w_lin = (const float*)d_in[5];
    const float* b_lin = (const float*)d_in[6];

    float* out    = (float*)d_out;                 // [B, T]
    float* states = out + (size_t)B * T;           // [B, T, H]

    gru_kernel<<<B, 128>>>(x, w_ih, w_hh, b_ih, b_hh, states);
    head_kernel<<<(B * T) / 256, 256>>>(x, states, w_lin, b_lin, out);
}